// round 10
// baseline (speedup 1.0000x reference)
#include <cuda_runtime.h>
#include <cuda_fp16.h>
#include <cstdint>
#include <cstddef>

// ----------------------------------------------------------------------------
// Problem dims (fixed by the reference)
// ----------------------------------------------------------------------------
static constexpr int BSZ   = 2048;
static constexpr int NCPG  = 20000;
static constexpr int NGENE = 4000;
static constexpr int NPATH = 500;
static constexpr int NGENE_PAD = 4096;
static constexpr int NPATH_PAD = 512;
static constexpr int K1PAD = 20032;   // NCPG padded to 64 (tail zeros)
static constexpr int K2PAD = 4032;    // NGENE padded to 64

// Scratch (device globals: allocation-free rule)
__device__ __half g_W1T[(size_t)NGENE_PAD * K1PAD];  // (W1*mask)^T fp16, [n][k]
__device__ __half g_W2T[(size_t)NPATH_PAD * K2PAD];  // (W2*mask)^T fp16
__device__ __half g_H  [(size_t)BSZ * K2PAD];        // layer-1 activations fp16, K-padded

#define DINL __device__ __forceinline__

DINL uint32_t smem_u32(const void* p) {
    uint32_t a;
    asm("{ .reg .u64 t; cvta.to.shared.u64 t, %1; cvt.u32.u64 %0, t; }" : "=r"(a) : "l"(p));
    return a;
}

#define CP_ASYNC16(dst, src) \
    asm volatile("cp.async.cg.shared.global [%0], [%1], 16;" :: "r"(dst), "l"(src))
#define CP_COMMIT() asm volatile("cp.async.commit_group;" ::: "memory")
#define CP_WAIT(n)  asm volatile("cp.async.wait_group %0;" :: "n"(n) : "memory")

#define LDSM_X4(r, addr)                                                        \
    asm volatile("ldmatrix.sync.aligned.m8n8.x4.shared.b16 {%0,%1,%2,%3}, [%4];"\
        : "=r"((r)[0]), "=r"((r)[1]), "=r"((r)[2]), "=r"((r)[3]) : "r"(addr))

#define STS128(a, b, c, d, addr) \
    asm volatile("st.shared.v4.b32 [%0], {%1, %2, %3, %4};" \
                 :: "r"(addr), "r"(a), "r"(b), "r"(c), "r"(d) : "memory")

DINL void mma_f16(float* d, const uint32_t* a, const uint32_t* b) {
    asm volatile(
        "mma.sync.aligned.m16n8k16.row.col.f32.f16.f16.f32 "
        "{%0,%1,%2,%3}, {%4,%5,%6,%7}, {%8,%9}, {%0,%1,%2,%3};"
        : "+f"(d[0]), "+f"(d[1]), "+f"(d[2]), "+f"(d[3])
        : "r"(a[0]), "r"(a[1]), "r"(a[2]), "r"(a[3]), "r"(b[0]), "r"(b[1]));
}

// ----------------------------------------------------------------------------
// Premask + transpose to fp16: WT[n][k] = h( W[k][n] * M[k][n] ); zero padding.
// ----------------------------------------------------------------------------
__global__ void premask_transpose_h(const float* __restrict__ W, const float* __restrict__ Mk,
                                    __half* __restrict__ WT, int K, int Kpad, int N) {
    __shared__ float tile[32][33];
    const int k0 = blockIdx.x * 32, n0 = blockIdx.y * 32;
    const int tx = threadIdx.x, ty = threadIdx.y;  // 32 x 8
#pragma unroll
    for (int j = 0; j < 32; j += 8) {
        const int k = k0 + ty + j, n = n0 + tx;
        float v = 0.0f;
        if (k < K && n < N) v = W[(size_t)k * N + n] * Mk[(size_t)k * N + n];
        tile[ty + j][tx] = v;
    }
    __syncthreads();
#pragma unroll
    for (int j = 0; j < 32; j += 8) {
        const int n = n0 + ty + j, k = k0 + tx;
        WT[(size_t)n * Kpad + k] = __float2half_rn(tile[tx][ty + j]);
    }
}

// ----------------------------------------------------------------------------
// GEMM: Out = epi( A[M,K] @ Bt[N,K]^T ), fp16 mma m16n8k16, fp32 accum.
// BM=128, BN template (256 L1 / 128 L2), BK=64 halves, 4 stages, 256 threads.
// Warp layout 2(M) x 4(N); warp tile 64 x (BN/4). Fragments via ldmatrix.x4.
// CVTA==true : A is fp32 (the harness x buffer, row stride KA); producer does
//              LDG.128 x2 + cvt to fp16 + swizzled STS (k>=KA chunks -> zeros).
// CVTA==false: A is fp16 (row stride = Kdim), producer uses cp.async.
// LAYER==1: v = relu(acc+bias)*inv + sh  -> half   (Out = g_H, ldo = K2PAD)
// LAYER==2: v = tanh((acc+bias)*inv+sh)  -> float  (Out = d_out, ldo = NPATH)
// ----------------------------------------------------------------------------
template <int BN, int LAYER, bool CVTA>
__global__ __launch_bounds__(256, 1)
void binn_gemm(const void* __restrict__ AV, const __half* __restrict__ Bt,
               void* __restrict__ OutV, int Kdim, int KA, int Nvalid, int ldo,
               const float* __restrict__ bias, const float* __restrict__ gamma,
               const float* __restrict__ beta, const float* __restrict__ mean,
               const float* __restrict__ var) {
    constexpr int BM = 128, BK = 64, S = 4;
    constexpr int WN = BN / 4;
    constexpr int NT = WN / 8;
    constexpr int NP = NT / 2;
    constexpr int MT = 4;
    constexpr uint32_t ASTG = BM * 128;   // bytes per A stage (64 halves = 128B/row)
    constexpr uint32_t BSTG = BN * 128;
    constexpr uint32_t STG  = ASTG + BSTG;

    extern __shared__ char dsm[];
    float* s_inv  = reinterpret_cast<float*>(dsm + S * STG);
    float* s_sh   = s_inv + BN;
    float* s_bias = s_sh + BN;

    const int tid = threadIdx.x;
    const int wid = tid >> 5, lane = tid & 31;
    const int wm = wid & 1, wn = wid >> 1;
    const int l4 = lane & 3, l2 = lane >> 2;
    const int m0 = blockIdx.y * BM, n0 = blockIdx.x * BN;

    if (tid < BN) {
        const int n = n0 + tid;
        const bool v = n < Nvalid;
        const float g  = v ? gamma[n] : 1.0f;
        const float vv = v ? var[n]   : 1.0f;
        const float be = v ? beta[n]  : 0.0f;
        const float mu = v ? mean[n]  : 0.0f;
        const float bi = v ? bias[n]  : 0.0f;
        const float inv = g * rsqrtf(vv + 1e-3f);
        s_inv[tid] = inv; s_sh[tid] = be - mu * inv; s_bias[tid] = bi;
    }

    const float*  Af = CVTA ? (const float*)AV + (size_t)m0 * KA : nullptr;
    const __half* Ah = CVTA ? nullptr : (const __half*)AV + (size_t)m0 * Kdim;
    const __half* Bb = Bt + (size_t)n0 * Kdim;
    const uint32_t sbase = smem_u32(dsm);

    auto load_stage = [&](int buf, int kt) {
        const uint32_t abase = sbase + buf * STG;
#pragma unroll
        for (int i = 0; i < BM * 8 / 256; ++i) {
            const int idx = i * 256 + tid;
            const int r = idx >> 3, ch = idx & 7;
            const uint32_t dst = abase + r * 128 + ((ch ^ (r & 7)) << 4);
            if (CVTA) {
                const int k0 = kt * BK + ch * 8;
                if (k0 < KA) {   // KA % 8 == 0: chunk fully valid or fully pad
                    const float4 v1 = *reinterpret_cast<const float4*>(Af + (size_t)r * KA + k0);
                    const float4 v2 = *reinterpret_cast<const float4*>(Af + (size_t)r * KA + k0 + 4);
                    const __half2 h0 = __floats2half2_rn(v1.x, v1.y);
                    const __half2 h1 = __floats2half2_rn(v1.z, v1.w);
                    const __half2 h2 = __floats2half2_rn(v2.x, v2.y);
                    const __half2 h3 = __floats2half2_rn(v2.z, v2.w);
                    STS128(*(const uint32_t*)&h0, *(const uint32_t*)&h1,
                           *(const uint32_t*)&h2, *(const uint32_t*)&h3, dst);
                } else {
                    STS128(0u, 0u, 0u, 0u, dst);
                }
            } else {
                CP_ASYNC16(dst, Ah + (size_t)r * Kdim + kt * BK + ch * 8);
            }
        }
        const uint32_t bbase = abase + ASTG;
        const __half* bg = Bb + kt * BK;
#pragma unroll
        for (int i = 0; i < BN * 8 / 256; ++i) {
            const int idx = i * 256 + tid;
            const int r = idx >> 3, ch = idx & 7;
            const uint32_t dst = bbase + r * 128 + ((ch ^ (r & 7)) << 4);
            CP_ASYNC16(dst, bg + (size_t)r * Kdim + ch * 8);
        }
    };

    const int T = Kdim / BK;
#pragma unroll
    for (int s = 0; s < S - 1; ++s) { load_stage(s, s); CP_COMMIT(); }

    float acc[MT * NT * 4];
#pragma unroll
    for (int i = 0; i < MT * NT * 4; ++i) acc[i] = 0.0f;

    const uint32_t lsw   = lane & 7;
    const uint32_t aoffL = (uint32_t)(wm * 64 + (lane & 15)) * 128;
    const uint32_t boffL = (uint32_t)(wn * WN + (lane & 7) + ((lane >> 4) << 3)) * 128;
    const uint32_t cAL   = (uint32_t)(lane >> 4);
    const uint32_t cBL   = (uint32_t)((lane >> 3) & 1);

    for (int t = 0; t < T; ++t) {
        CP_WAIT(S - 2);          // stage t's cp.async data resident
        __syncthreads();         // orders STS (A) and prior-stage reads
        if (t + S - 1 < T) load_stage((t + S - 1) % S, t + S - 1);
        CP_COMMIT();             // unconditional: uniform group accounting

        const uint32_t apS = sbase + (t % S) * STG;
        const uint32_t bpS = apS + ASTG;
#pragma unroll
        for (int kk = 0; kk < 4; ++kk) {
            const uint32_t swA = (((uint32_t)(kk * 2) + cAL) ^ lsw) << 4;
            const uint32_t swB = (((uint32_t)(kk * 2) + cBL) ^ lsw) << 4;
            uint32_t a[MT][4], b[NP][4];
#pragma unroll
            for (int mt = 0; mt < MT; ++mt)
                LDSM_X4(a[mt], apS + aoffL + mt * 2048 + swA);
#pragma unroll
            for (int p = 0; p < NP; ++p)
                LDSM_X4(b[p], bpS + boffL + p * 2048 + swB);
#pragma unroll
            for (int mt = 0; mt < MT; ++mt)
#pragma unroll
                for (int nt = 0; nt < NT; ++nt)
                    mma_f16(&acc[(mt * NT + nt) * 4], a[mt], &b[nt >> 1][(nt & 1) * 2]);
        }
    }

    // ---------------- Epilogue ----------------
#pragma unroll
    for (int mt = 0; mt < MT; ++mt) {
#pragma unroll
        for (int nt = 0; nt < NT; ++nt) {
            const float* d = &acc[(mt * NT + nt) * 4];
            const int ncol = wn * WN + nt * 8 + l4 * 2;
            const int n = n0 + ncol;
#pragma unroll
            for (int half = 0; half < 2; ++half) {
                const int m = m0 + wm * 64 + mt * 16 + l2 + half * 8;
                float v0 = d[half * 2 + 0] + s_bias[ncol];
                float v1 = d[half * 2 + 1] + s_bias[ncol + 1];
                if (LAYER == 1) {
                    v0 = fmaxf(v0, 0.0f) * s_inv[ncol]     + s_sh[ncol];
                    v1 = fmaxf(v1, 0.0f) * s_inv[ncol + 1] + s_sh[ncol + 1];
                    if (n < ldo) {   // ldo = K2PAD; zero the K-pad columns of g_H
                        const __half2 o = __floats2half2_rn(n < Nvalid ? v0 : 0.0f,
                                                            n + 1 < Nvalid ? v1 : 0.0f);
                        *reinterpret_cast<__half2*>((__half*)OutV + (size_t)m * ldo + n) = o;
                    }
                } else {
                    v0 = tanhf(v0 * s_inv[ncol]     + s_sh[ncol]);
                    v1 = tanhf(v1 * s_inv[ncol + 1] + s_sh[ncol + 1]);
                    if (n < Nvalid) {  // Nvalid even -> pair never straddles
                        float2 o; o.x = v0; o.y = v1;
                        *reinterpret_cast<float2*>((float*)OutV + (size_t)m * ldo + n) = o;
                    }
                }
            }
        }
    }
}

// ----------------------------------------------------------------------------
// kernel_launch
// ----------------------------------------------------------------------------
extern "C" void kernel_launch(void* const* d_in, const int* in_sizes, int n_in,
                              void* d_out, int out_size) {
    const float* x      = (const float*)d_in[0];
    const float* m1     = (const float*)d_in[1];
    const float* m2     = (const float*)d_in[2];
    const float* W1     = (const float*)d_in[3];
    const float* b1     = (const float*)d_in[4];
    const float* W2     = (const float*)d_in[5];
    const float* b2     = (const float*)d_in[6];
    const float* gamma1 = (const float*)d_in[7];
    const float* beta1  = (const float*)d_in[8];
    const float* mean1  = (const float*)d_in[9];
    const float* var1   = (const float*)d_in[10];
    const float* gamma2 = (const float*)d_in[11];
    const float* beta2  = (const float*)d_in[12];
    const float* mean2  = (const float*)d_in[13];
    const float* var2   = (const float*)d_in[14];

    __half *w1t, *w2t, *h;
    cudaGetSymbolAddress((void**)&w1t, g_W1T);
    cudaGetSymbolAddress((void**)&w2t, g_W2T);
    cudaGetSymbolAddress((void**)&h,   g_H);

    const int smem1 = 4 * (128 * 128 + 256 * 128) + 3 * 256 * 4;  // 199680
    const int smem2 = 4 * (128 * 128 + 128 * 128) + 3 * 128 * 4;  // 132608
    cudaFuncSetAttribute(binn_gemm<256, 1, true>,
                         cudaFuncAttributeMaxDynamicSharedMemorySize, smem1);
    cudaFuncSetAttribute(binn_gemm<128, 2, false>,
                         cudaFuncAttributeMaxDynamicSharedMemorySize, smem2);

    // 1) masked, transposed fp16 weights (K- and N-padded)
    const dim3 tb(32, 8);
    premask_transpose_h<<<dim3(K1PAD / 32, NGENE_PAD / 32), tb>>>(W1, m1, w1t, NCPG,  K1PAD, NGENE);
    premask_transpose_h<<<dim3(K2PAD / 32, NPATH_PAD / 32), tb>>>(W2, m2, w2t, NGENE, K2PAD, NPATH);

    // 2) GEMM1: h = fp16( BN1(relu(x @ W1m + b1)) ), x read fp32 directly
    binn_gemm<256, 1, true><<<dim3(NGENE_PAD / 256, BSZ / 128), 256, smem1>>>(
        x, w1t, h, K1PAD, NCPG, NGENE, K2PAD, b1, gamma1, beta1, mean1, var1);

    // 3) GEMM2: out = tanh(BN2(h @ W2m + b2))
    binn_gemm<128, 2, false><<<dim3(NPATH_PAD / 128, BSZ / 128), 256, smem2>>>(
        h, w2t, d_out, K2PAD, K2PAD, NPATH, NPATH, b2, gamma2, beta2, mean2, var2);
}

// round 13
// speedup vs baseline: 1.3767x; 1.3767x over previous
#include <cuda_runtime.h>
#include <cuda_fp16.h>
#include <cstdint>
#include <cstddef>

// ----------------------------------------------------------------------------
// Problem dims (fixed by the reference)
// ----------------------------------------------------------------------------
static constexpr int BSZ   = 2048;
static constexpr int NCPG  = 20000;
static constexpr int NGENE = 4000;
static constexpr int NPATH = 500;
static constexpr int NGENE_PAD = 4096;
static constexpr int NPATH_PAD = 512;
static constexpr int K1PAD = 20032;   // NCPG padded to 64
static constexpr int K2PAD = 4032;    // NGENE padded to 64

// Scratch (device globals: allocation-free rule)
__device__ __half g_X  [(size_t)BSZ * K1PAD];        // x -> fp16, K-padded
__device__ __half g_W1T[(size_t)NGENE_PAD * K1PAD];  // (W1*mask)^T fp16, [n][k]
__device__ __half g_W2T[(size_t)NPATH_PAD * K2PAD];  // (W2*mask)^T fp16
__device__ __half g_H  [(size_t)BSZ * K2PAD];        // layer-1 activations fp16, K-padded

#define DINL __device__ __forceinline__

DINL uint32_t smem_u32(const void* p) {
    uint32_t a;
    asm("{ .reg .u64 t; cvta.to.shared.u64 t, %1; cvt.u32.u64 %0, t; }" : "=r"(a) : "l"(p));
    return a;
}

#define CP_ASYNC16(dst, src) \
    asm volatile("cp.async.cg.shared.global [%0], [%1], 16;" :: "r"(dst), "l"(src))
#define CP_COMMIT() asm volatile("cp.async.commit_group;" ::: "memory")
#define CP_WAIT(n)  asm volatile("cp.async.wait_group %0;" :: "n"(n) : "memory")

#define LDSM_X4(r, addr)                                                        \
    asm volatile("ldmatrix.sync.aligned.m8n8.x4.shared.b16 {%0,%1,%2,%3}, [%4];"\
        : "=r"((r)[0]), "=r"((r)[1]), "=r"((r)[2]), "=r"((r)[3]) : "r"(addr))

DINL void mma_f16(float* d, const uint32_t* a, const uint32_t* b) {
    asm volatile(
        "mma.sync.aligned.m16n8k16.row.col.f32.f16.f16.f32 "
        "{%0,%1,%2,%3}, {%4,%5,%6,%7}, {%8,%9}, {%0,%1,%2,%3};"
        : "+f"(d[0]), "+f"(d[1]), "+f"(d[2]), "+f"(d[3])
        : "r"(a[0]), "r"(a[1]), "r"(a[2]), "r"(a[3]), "r"(b[0]), "r"(b[1]));
}

// ----------------------------------------------------------------------------
// Premask + transpose to fp16: WT[n][k] = h( W[k][n] * M[k][n] ); zero padding.
// ----------------------------------------------------------------------------
__global__ void premask_transpose_h(const float* __restrict__ W, const float* __restrict__ Mk,
                                    __half* __restrict__ WT, int K, int Kpad, int N) {
    __shared__ float tile[32][33];
    const int k0 = blockIdx.x * 32, n0 = blockIdx.y * 32;
    const int tx = threadIdx.x, ty = threadIdx.y;  // 32 x 8
#pragma unroll
    for (int j = 0; j < 32; j += 8) {
        const int k = k0 + ty + j, n = n0 + tx;
        float v = 0.0f;
        if (k < K && n < N) v = W[(size_t)k * N + n] * Mk[(size_t)k * N + n];
        tile[ty + j][tx] = v;
    }
    __syncthreads();
#pragma unroll
    for (int j = 0; j < 32; j += 8) {
        const int n = n0 + ty + j, k = k0 + tx;
        WT[(size_t)n * Kpad + k] = __float2half_rn(tile[tx][ty + j]);
    }
}

// ----------------------------------------------------------------------------
// x (fp32) -> fp16, K-padded with zeros. One thread = 8 output halves (16B).
// ----------------------------------------------------------------------------
__global__ void round_x_h(const float* __restrict__ in, __half* __restrict__ out,
                          int K, int Kpad) {
    const int c = blockIdx.x * blockDim.x + threadIdx.x;  // 8-elem chunk
    const int row = blockIdx.y;
    if (c >= Kpad / 8) return;
    const int col0 = c * 8;
    __half h[8];
    if (col0 + 8 <= K) {
        const float4 v1 = reinterpret_cast<const float4*>(in + (size_t)row * K + col0)[0];
        const float4 v2 = reinterpret_cast<const float4*>(in + (size_t)row * K + col0)[1];
        h[0] = __float2half_rn(v1.x); h[1] = __float2half_rn(v1.y);
        h[2] = __float2half_rn(v1.z); h[3] = __float2half_rn(v1.w);
        h[4] = __float2half_rn(v2.x); h[5] = __float2half_rn(v2.y);
        h[6] = __float2half_rn(v2.z); h[7] = __float2half_rn(v2.w);
    } else {
#pragma unroll
        for (int e = 0; e < 8; ++e) {
            const int col = col0 + e;
            h[e] = (col < K) ? __float2half_rn(in[(size_t)row * K + col]) : __half(0.0f);
        }
    }
    *reinterpret_cast<uint4*>(out + (size_t)row * Kpad + col0) = *reinterpret_cast<uint4*>(h);
}

// ----------------------------------------------------------------------------
// GEMM: Out = epi( A[M,K] @ Bt[N,K]^T ), fp16 mma m16n8k16, fp32 accum.
// Tile BM x BN, BK=64 halves (128B rows), 4 stages, 256 threads.
// Warp layout 2(M) x 4(N); warp tile (BM/2) x (BN/4). Fragments via ldmatrix.x4.
// GEMM1: BM=128,BN=256, 1 CTA/SM. GEMM2: BM=64,BN=128, 2 CTAs/SM (1 full wave).
// LAYER==1: v = relu(acc+bias)*inv + sh  -> half   (Out = g_H, ldo = K2PAD)
// LAYER==2: v = tanh((acc+bias)*inv+sh)  -> float  (Out = d_out, ldo = NPATH)
// ----------------------------------------------------------------------------
template <int BM, int BN, int LAYER, int MAXCTA>
__global__ __launch_bounds__(256, MAXCTA)
void binn_gemm(const __half* __restrict__ A, const __half* __restrict__ Bt,
               void* __restrict__ OutV, int Kdim, int Nvalid, int ldo,
               const float* __restrict__ bias, const float* __restrict__ gamma,
               const float* __restrict__ beta, const float* __restrict__ mean,
               const float* __restrict__ var) {
    constexpr int BK = 64, S = 4;
    constexpr int WM = BM / 2;            // warp m-tile extent
    constexpr int WN = BN / 4;            // warp n-tile extent
    constexpr int MT = WM / 16;           // m16 tiles per warp
    constexpr int NT = WN / 8;            // n8 tiles per warp
    constexpr int NP = NT / 2;            // ldmatrix pairs for B
    constexpr uint32_t ASTG = BM * 128;   // bytes per A stage (64 halves = 128B/row)
    constexpr uint32_t BSTG = BN * 128;
    constexpr uint32_t STG  = ASTG + BSTG;

    extern __shared__ char dsm[];
    float* s_inv  = reinterpret_cast<float*>(dsm + S * STG);
    float* s_sh   = s_inv + BN;
    float* s_bias = s_sh + BN;

    const int tid = threadIdx.x;
    const int wid = tid >> 5, lane = tid & 31;
    const int wm = wid & 1, wn = wid >> 1;
    const int l4 = lane & 3, l2 = lane >> 2;
    const int m0 = blockIdx.y * BM, n0 = blockIdx.x * BN;

    if (tid < BN) {
        const int n = n0 + tid;
        const bool v = n < Nvalid;
        const float g  = v ? gamma[n] : 1.0f;
        const float vv = v ? var[n]   : 1.0f;
        const float be = v ? beta[n]  : 0.0f;
        const float mu = v ? mean[n]  : 0.0f;
        const float bi = v ? bias[n]  : 0.0f;
        const float inv = g * rsqrtf(vv + 1e-3f);
        s_inv[tid] = inv; s_sh[tid] = be - mu * inv; s_bias[tid] = bi;
    }

    const __half* Ab = A + (size_t)m0 * Kdim;
    const __half* Bb = Bt + (size_t)n0 * Kdim;
    const uint32_t sbase = smem_u32(dsm);

    auto load_stage = [&](int buf, int kt) {
        const uint32_t abase = sbase + buf * STG;
        const __half* ag = Ab + kt * BK;
#pragma unroll
        for (int i = 0; i < BM * 8 / 256; ++i) {
            const int idx = i * 256 + tid;
            const int r = idx >> 3, ch = idx & 7;
            const uint32_t dst = abase + r * 128 + ((ch ^ (r & 7)) << 4);
            CP_ASYNC16(dst, ag + (size_t)r * Kdim + ch * 8);
        }
        const uint32_t bbase = abase + ASTG;
        const __half* bg = Bb + kt * BK;
#pragma unroll
        for (int i = 0; i < BN * 8 / 256; ++i) {
            const int idx = i * 256 + tid;
            const int r = idx >> 3, ch = idx & 7;
            const uint32_t dst = bbase + r * 128 + ((ch ^ (r & 7)) << 4);
            CP_ASYNC16(dst, bg + (size_t)r * Kdim + ch * 8);
        }
    };

    const int T = Kdim / BK;
#pragma unroll
    for (int s = 0; s < S - 1; ++s) { load_stage(s, s); CP_COMMIT(); }

    float acc[MT * NT * 4];
#pragma unroll
    for (int i = 0; i < MT * NT * 4; ++i) acc[i] = 0.0f;

    // ldmatrix per-lane constants (swizzle XOR term reduces to lane&7)
    const uint32_t lsw   = lane & 7;
    const uint32_t aoffL = (uint32_t)(wm * WM + (lane & 15)) * 128;
    const uint32_t boffL = (uint32_t)(wn * WN + (lane & 7) + ((lane >> 4) << 3)) * 128;
    const uint32_t cAL   = (uint32_t)(lane >> 4);
    const uint32_t cBL   = (uint32_t)((lane >> 3) & 1);

    for (int t = 0; t < T; ++t) {
        CP_WAIT(S - 2);          // stage t resident
        __syncthreads();         // all warps done with iter t-1's stage reads
        if (t + S - 1 < T) load_stage((t + S - 1) % S, t + S - 1);
        CP_COMMIT();             // unconditional: uniform group accounting

        const uint32_t apS = sbase + (t % S) * STG;
        const uint32_t bpS = apS + ASTG;
#pragma unroll
        for (int kk = 0; kk < 4; ++kk) {
            const uint32_t swA = (((uint32_t)(kk * 2) + cAL) ^ lsw) << 4;
            const uint32_t swB = (((uint32_t)(kk * 2) + cBL) ^ lsw) << 4;
            uint32_t a[MT][4], b[NP][4];
#pragma unroll
            for (int mt = 0; mt < MT; ++mt)
                LDSM_X4(a[mt], apS + aoffL + mt * 2048 + swA);
#pragma unroll
            for (int p = 0; p < NP; ++p)
                LDSM_X4(b[p], bpS + boffL + p * 2048 + swB);
#pragma unroll
            for (int mt = 0; mt < MT; ++mt)
#pragma unroll
                for (int nt = 0; nt < NT; ++nt)
                    mma_f16(&acc[(mt * NT + nt) * 4], a[mt], &b[nt >> 1][(nt & 1) * 2]);
        }
    }

    // ---------------- Epilogue ----------------
#pragma unroll
    for (int mt = 0; mt < MT; ++mt) {
#pragma unroll
        for (int nt = 0; nt < NT; ++nt) {
            const float* d = &acc[(mt * NT + nt) * 4];
            const int ncol = wn * WN + nt * 8 + l4 * 2;
            const int n = n0 + ncol;
#pragma unroll
            for (int half = 0; half < 2; ++half) {
                const int m = m0 + wm * WM + mt * 16 + l2 + half * 8;
                float v0 = d[half * 2 + 0] + s_bias[ncol];
                float v1 = d[half * 2 + 1] + s_bias[ncol + 1];
                if (LAYER == 1) {
                    v0 = fmaxf(v0, 0.0f) * s_inv[ncol]     + s_sh[ncol];
                    v1 = fmaxf(v1, 0.0f) * s_inv[ncol + 1] + s_sh[ncol + 1];
                    if (n < ldo) {   // ldo = K2PAD; zero the K-pad columns of g_H
                        const __half2 o = __floats2half2_rn(n < Nvalid ? v0 : 0.0f,
                                                            n + 1 < Nvalid ? v1 : 0.0f);
                        *reinterpret_cast<__half2*>((__half*)OutV + (size_t)m * ldo + n) = o;
                    }
                } else {
                    v0 = tanhf(v0 * s_inv[ncol]     + s_sh[ncol]);
                    v1 = tanhf(v1 * s_inv[ncol + 1] + s_sh[ncol + 1]);
                    if (n < Nvalid) {  // Nvalid even -> pair never straddles
                        float2 o; o.x = v0; o.y = v1;
                        *reinterpret_cast<float2*>((float*)OutV + (size_t)m * ldo + n) = o;
                    }
                }
            }
        }
    }
}

// ----------------------------------------------------------------------------
// kernel_launch
// ----------------------------------------------------------------------------
extern "C" void kernel_launch(void* const* d_in, const int* in_sizes, int n_in,
                              void* d_out, int out_size) {
    const float* x      = (const float*)d_in[0];
    const float* m1     = (const float*)d_in[1];
    const float* m2     = (const float*)d_in[2];
    const float* W1     = (const float*)d_in[3];
    const float* b1     = (const float*)d_in[4];
    const float* W2     = (const float*)d_in[5];
    const float* b2     = (const float*)d_in[6];
    const float* gamma1 = (const float*)d_in[7];
    const float* beta1  = (const float*)d_in[8];
    const float* mean1  = (const float*)d_in[9];
    const float* var1   = (const float*)d_in[10];
    const float* gamma2 = (const float*)d_in[11];
    const float* beta2  = (const float*)d_in[12];
    const float* mean2  = (const float*)d_in[13];
    const float* var2   = (const float*)d_in[14];

    __half *xh, *w1t, *w2t, *h;
    cudaGetSymbolAddress((void**)&xh,  g_X);
    cudaGetSymbolAddress((void**)&w1t, g_W1T);
    cudaGetSymbolAddress((void**)&w2t, g_W2T);
    cudaGetSymbolAddress((void**)&h,   g_H);

    const int smem1 = 4 * (128 * 128 + 256 * 128) + 3 * 256 * 4;  // 199680
    const int smem2 = 4 * (64 * 128 + 128 * 128) + 3 * 128 * 4;   //  99840 (x2/SM)
    cudaFuncSetAttribute(binn_gemm<128, 256, 1, 1>,
                         cudaFuncAttributeMaxDynamicSharedMemorySize, smem1);
    cudaFuncSetAttribute(binn_gemm<64, 128, 2, 2>,
                         cudaFuncAttributeMaxDynamicSharedMemorySize, smem2);

    // 1) x -> fp16 (K-padded)
    round_x_h<<<dim3((K1PAD / 8 + 255) / 256, BSZ), 256>>>(x, xh, NCPG, K1PAD);

    // 2) masked, transposed fp16 weights (K- and N-padded)
    const dim3 tb(32, 8);
    premask_transpose_h<<<dim3(K1PAD / 32, NGENE_PAD / 32), tb>>>(W1, m1, w1t, NCPG,  K1PAD, NGENE);
    premask_transpose_h<<<dim3(K2PAD / 32, NPATH_PAD / 32), tb>>>(W2, m2, w2t, NGENE, K2PAD, NPATH);

    // 3) GEMM1: h = fp16( BN1(relu(x @ W1m + b1)) )  [R7 config: BM=128, BN=256]
    binn_gemm<128, 256, 1, 1><<<dim3(NGENE_PAD / 256, BSZ / 128), 256, smem1>>>(
        xh, w1t, h, K1PAD, NGENE, K2PAD, b1, gamma1, beta1, mean1, var1);

    // 4) GEMM2: out = tanh(BN2(h @ W2m + b2))  [BM=64: 128 CTAs, one full wave]
    binn_gemm<64, 128, 2, 2><<<dim3(NPATH_PAD / 128, BSZ / 64), 256, smem2>>>(
        h, w2t, d_out, K2PAD, NPATH, NPATH, b2, gamma2, beta2, mean2, var2);
}